// round 7
// baseline (speedup 1.0000x reference)
#include <cuda_runtime.h>
#include <math.h>
#include <float.h>

#define D        64
#define TJ       64
#define ROWS     64
#define SPLIT    4
#define NTHREADS 256
#define KMAX     16
#define MAXB     16384
#define MAXC     64

__device__ float g_sq[MAXB];
__device__ int   g_hard[MAXB];
__device__ int   g_counts[MAXC];

__global__ void zero_kernel() {
    if (threadIdx.x < MAXC) g_counts[threadIdx.x] = 0;
}

// Per-row: argmax/max over categorical, global cluster histogram, squared norms.
__global__ void prep_kernel(const float* __restrict__ enc,
                            const float* __restrict__ cat,
                            float* __restrict__ out, int B, int NC) {
    int i = blockIdx.x * blockDim.x + threadIdx.x;
    if (i >= B) return;

    float mv = cat[(size_t)i * NC];
    int   mi = 0;
    for (int c = 1; c < NC; c++) {
        float v = cat[(size_t)i * NC + c];
        if (v > mv) { mv = v; mi = c; }   // strict > keeps first max (argmax semantics)
    }
    g_hard[i] = mi;
    atomicAdd(&g_counts[mi], 1);
    out[(size_t)B * D + B + 2 + i] = mv;  // max_groups

    float s = 0.f;
    #pragma unroll
    for (int d = 0; d < D; d++) {
        float v = enc[(size_t)i * D + d];
        s = fmaf(v, v, s);
    }
    g_sq[i] = s;
}

// Fused distance GEMM + online top-16 selection + neighborhood entropy.
// One thread per (row, J-split). 64 rows/CTA, 4-way J split, 256 threads.
__global__ __launch_bounds__(NTHREADS, 1)
void knn_kernel(const float* __restrict__ enc, const int* __restrict__ kptr,
                float* __restrict__ out, int B, int NC) {
    // Phase 1 layout: tile[TJ*D] + tsq[TJ]  (4160 floats)
    // Phase 2 layout: mval[64*ROWS] + midx[64*ROWS] (8192 words)
    __shared__ float sm[2 * 64 * ROWS];
    float* tile = sm;
    float* tsq  = sm + TJ * D;
    float* mval = sm;
    int*   midx = (int*)(sm + 64 * ROWS);

    const int tid = threadIdx.x;
    const int r   = tid & (ROWS - 1);
    const int s   = tid >> 6;          // J-split id 0..3
    const int row = blockIdx.x * ROWS + r;

    // Own encoding in registers
    float a[D];
    #pragma unroll
    for (int d = 0; d < D; d += 4) {
        float4 v = *(const float4*)(enc + (size_t)row * D + d);
        a[d] = v.x; a[d + 1] = v.y; a[d + 2] = v.z; a[d + 3] = v.w;
    }
    float sqi = 0.f;
    #pragma unroll
    for (int d = 0; d < D; d++) sqi = fmaf(a[d], a[d], sqi);

    // Top-16 (value, index), sorted ascending, fully register-resident.
    float bval[KMAX];
    int   bidx[KMAX];
    #pragma unroll
    for (int t = 0; t < KMAX; t++) { bval[t] = FLT_MAX; bidx[t] = 0; }

    for (int jt = 0; jt < B; jt += TJ) {
        __syncthreads();
        // Cooperative tile load (coalesced float4)
        for (int u = tid; u < (TJ * D) / 4; u += NTHREADS)
            ((float4*)tile)[u] = ((const float4*)(enc + (size_t)jt * D))[u];
        if (tid < TJ) tsq[tid] = g_sq[jt + tid];
        __syncthreads();

        for (int jj = s; jj < TJ; jj += SPLIT) {
            const float* bp = tile + jj * D;   // warp-uniform -> broadcast LDS
            float a0 = 0.f, a1 = 0.f, a2 = 0.f, a3 = 0.f;
            #pragma unroll
            for (int d = 0; d < D; d += 4) {
                a0 = fmaf(a[d],     bp[d],     a0);
                a1 = fmaf(a[d + 1], bp[d + 1], a1);
                a2 = fmaf(a[d + 2], bp[d + 2], a2);
                a3 = fmaf(a[d + 3], bp[d + 3], a3);
            }
            float dot = (a0 + a1) + (a2 + a3);
            float d2v = fmaxf(fmaf(dot, -2.f, tsq[jj] + sqi), 0.f);

            if (d2v < bval[KMAX - 1]) {        // cheap reject: 1 compare/candidate
                float cv = d2v;
                int   ci = jt + jj;
                #pragma unroll
                for (int t = 0; t < KMAX; t++) {   // register swap-chain insert
                    if (cv < bval[t]) {
                        float tv = bval[t]; bval[t] = cv; cv = tv;
                        int   ti = bidx[t]; bidx[t] = ci; ci = ti;
                    }
                }
            }
        }
    }

    // Dump per-split sorted lists (transposed: conflict-free merge reads)
    __syncthreads();
    #pragma unroll
    for (int t = 0; t < KMAX; t++) {
        int slot = s * KMAX + t;
        mval[slot * ROWS + r] = bval[t];
        midx[slot * ROWS + r] = bidx[t];
    }
    __syncthreads();

    // One thread per row: 4-way merge of sorted lists -> k+1 smallest, entropy.
    if (tid < ROWS) {
        const int rr   = tid;
        const int grow = blockIdx.x * ROWS + rr;
        int kk = *kptr;
        if (kk > B / 4)    kk = B / 4;
        if (kk > KMAX - 1) kk = KMAX - 1;

        int   p[SPLIT] = {0, 0, 0, 0};
        float vals[KMAX];
        int   inds[KMAX];
        for (int t = 0; t <= kk; t++) {
            float bv = FLT_MAX; int bs = 0;
            #pragma unroll
            for (int s2 = 0; s2 < SPLIT; s2++) {
                int ps = p[s2];
                float v = (ps < KMAX) ? mval[(s2 * KMAX + ps) * ROWS + rr] : FLT_MAX;
                if (v < bv) { bv = v; bs = s2; }
            }
            vals[t] = bv;
            inds[t] = midx[(bs * KMAX + p[bs]) * ROWS + rr];
            p[bs]++;
        }
        float kth = vals[kk];

        int cnt[MAXC];
        for (int c = 0; c < NC; c++) cnt[c] = 0;
        int n = 0;
        for (int t = 0; t < kk; t++) {
            if (vals[t] < kth) { cnt[g_hard[inds[t]]]++; n++; }
        }
        float inv = 1.f / (float)(n > 1 ? n : 1);
        float ent = 0.f;
        for (int c = 0; c < NC; c++) {
            float b = cnt[c] * inv;
            ent -= b * logf(b + 1e-5f);
        }
        out[(size_t)B * D + grow] = ent;   // neighbourhood_entropy
    }
}

__global__ void final_kernel(float* __restrict__ out, int B, int NC) {
    if (threadIdx.x == 0 && blockIdx.x == 0) {
        float invB = 1.f / (float)B;
        float ent = 0.f;
        int   np  = 0;
        for (int c = 0; c < NC; c++) {
            int g = g_counts[c];
            if (g > 0) np++;
            float b = g * invB;
            ent -= b * logf(b + 1e-5f);
        }
        out[(size_t)B * D + B]     = ent;        // cluster_size_entropy
        out[(size_t)B * D + B + 1] = (float)np;  // n_populated
    }
}

extern "C" void kernel_launch(void* const* d_in, const int* in_sizes, int n_in,
                              void* d_out, int out_size) {
    const float* enc  = (const float*)d_in[0];
    const float* cat  = (const float*)d_in[1];
    const int*   kptr = (const int*)d_in[2];
    float*       out  = (float*)d_out;

    int B  = in_sizes[0] / D;
    int NC = in_sizes[1] / B;

    // encodings passthrough
    cudaMemcpyAsync(d_out, d_in[0], (size_t)B * D * sizeof(float),
                    cudaMemcpyDeviceToDevice, 0);

    zero_kernel<<<1, MAXC>>>();
    prep_kernel<<<(B + 255) / 256, 256>>>(enc, cat, out, B, NC);
    knn_kernel<<<B / ROWS, NTHREADS>>>(enc, kptr, out, B, NC);
    final_kernel<<<1, 32>>>(out, B, NC);
}

// round 8
// speedup vs baseline: 1.0010x; 1.0010x over previous
#include <cuda_runtime.h>
#include <math.h>
#include <float.h>

#define D        64
#define TJ       64
#define ROWS     64
#define SPLIT    4
#define NTHREADS 256
#define KMAX     16
#define MAXB     16384
#define MAXC     64

__device__ float g_sq[MAXB];
__device__ int   g_hard[MAXB];
__device__ int   g_counts[MAXC];

__global__ void zero_kernel() {
    if (threadIdx.x < MAXC) g_counts[threadIdx.x] = 0;
}

// Per-row: argmax/max over categorical, global cluster histogram, squared norms.
__global__ void prep_kernel(const float* __restrict__ enc,
                            const float* __restrict__ cat,
                            float* __restrict__ out, int B, int NC) {
    int i = blockIdx.x * blockDim.x + threadIdx.x;
    if (i >= B) return;

    float mv = cat[(size_t)i * NC];
    int   mi = 0;
    for (int c = 1; c < NC; c++) {
        float v = cat[(size_t)i * NC + c];
        if (v > mv) { mv = v; mi = c; }   // strict > keeps first max (argmax semantics)
    }
    g_hard[i] = mi;
    atomicAdd(&g_counts[mi], 1);
    out[(size_t)B * D + B + 2 + i] = mv;  // max_groups

    float s = 0.f;
    #pragma unroll
    for (int d = 0; d < D; d++) {
        float v = enc[(size_t)i * D + d];
        s = fmaf(v, v, s);
    }
    g_sq[i] = s;
}

// Fused distance GEMM + online top-16 selection + neighborhood entropy.
// One thread per (row, J-split). 64 rows/CTA, 4-way J split, 256 threads.
__global__ __launch_bounds__(NTHREADS, 1)
void knn_kernel(const float* __restrict__ enc, const int* __restrict__ kptr,
                float* __restrict__ out, int B, int NC) {
    // Phase 1 layout: tile[TJ*D] + tsq[TJ]  (4160 floats)
    // Phase 2 layout: mval[64*ROWS] + midx[64*ROWS] (8192 words)
    __shared__ float sm[2 * 64 * ROWS];
    float* tile = sm;
    float* tsq  = sm + TJ * D;
    float* mval = sm;
    int*   midx = (int*)(sm + 64 * ROWS);

    const int tid = threadIdx.x;
    const int r   = tid & (ROWS - 1);
    const int s   = tid >> 6;          // J-split id 0..3
    const int row = blockIdx.x * ROWS + r;

    // Own encoding in registers
    float a[D];
    #pragma unroll
    for (int d = 0; d < D; d += 4) {
        float4 v = *(const float4*)(enc + (size_t)row * D + d);
        a[d] = v.x; a[d + 1] = v.y; a[d + 2] = v.z; a[d + 3] = v.w;
    }
    float sqi = 0.f;
    #pragma unroll
    for (int d = 0; d < D; d++) sqi = fmaf(a[d], a[d], sqi);

    // Top-16 (value, index), sorted ascending, fully register-resident.
    float bval[KMAX];
    int   bidx[KMAX];
    #pragma unroll
    for (int t = 0; t < KMAX; t++) { bval[t] = FLT_MAX; bidx[t] = 0; }

    for (int jt = 0; jt < B; jt += TJ) {
        __syncthreads();
        // Cooperative tile load (coalesced float4)
        for (int u = tid; u < (TJ * D) / 4; u += NTHREADS)
            ((float4*)tile)[u] = ((const float4*)(enc + (size_t)jt * D))[u];
        if (tid < TJ) tsq[tid] = g_sq[jt + tid];
        __syncthreads();

        for (int jj = s; jj < TJ; jj += SPLIT) {
            const float* bp = tile + jj * D;   // warp-uniform -> broadcast LDS
            float a0 = 0.f, a1 = 0.f, a2 = 0.f, a3 = 0.f;
            #pragma unroll
            for (int d = 0; d < D; d += 4) {
                a0 = fmaf(a[d],     bp[d],     a0);
                a1 = fmaf(a[d + 1], bp[d + 1], a1);
                a2 = fmaf(a[d + 2], bp[d + 2], a2);
                a3 = fmaf(a[d + 3], bp[d + 3], a3);
            }
            float dot = (a0 + a1) + (a2 + a3);
            float d2v = fmaxf(fmaf(dot, -2.f, tsq[jj] + sqi), 0.f);

            if (d2v < bval[KMAX - 1]) {        // cheap reject: 1 compare/candidate
                float cv = d2v;
                int   ci = jt + jj;
                #pragma unroll
                for (int t = 0; t < KMAX; t++) {   // register swap-chain insert
                    if (cv < bval[t]) {
                        float tv = bval[t]; bval[t] = cv; cv = tv;
                        int   ti = bidx[t]; bidx[t] = ci; ci = ti;
                    }
                }
            }
        }
    }

    // Dump per-split sorted lists (transposed: conflict-free merge reads)
    __syncthreads();
    #pragma unroll
    for (int t = 0; t < KMAX; t++) {
        int slot = s * KMAX + t;
        mval[slot * ROWS + r] = bval[t];
        midx[slot * ROWS + r] = bidx[t];
    }
    __syncthreads();

    // One thread per row: 4-way merge of sorted lists -> k+1 smallest, entropy.
    if (tid < ROWS) {
        const int rr   = tid;
        const int grow = blockIdx.x * ROWS + rr;
        int kk = *kptr;
        if (kk > B / 4)    kk = B / 4;
        if (kk > KMAX - 1) kk = KMAX - 1;

        int   p[SPLIT] = {0, 0, 0, 0};
        float vals[KMAX];
        int   inds[KMAX];
        for (int t = 0; t <= kk; t++) {
            float bv = FLT_MAX; int bs = 0;
            #pragma unroll
            for (int s2 = 0; s2 < SPLIT; s2++) {
                int ps = p[s2];
                float v = (ps < KMAX) ? mval[(s2 * KMAX + ps) * ROWS + rr] : FLT_MAX;
                if (v < bv) { bv = v; bs = s2; }
            }
            vals[t] = bv;
            inds[t] = midx[(bs * KMAX + p[bs]) * ROWS + rr];
            p[bs]++;
        }
        float kth = vals[kk];

        int cnt[MAXC];
        for (int c = 0; c < NC; c++) cnt[c] = 0;
        int n = 0;
        for (int t = 0; t < kk; t++) {
            if (vals[t] < kth) { cnt[g_hard[inds[t]]]++; n++; }
        }
        float inv = 1.f / (float)(n > 1 ? n : 1);
        float ent = 0.f;
        for (int c = 0; c < NC; c++) {
            float b = cnt[c] * inv;
            ent -= b * logf(b + 1e-5f);
        }
        out[(size_t)B * D + grow] = ent;   // neighbourhood_entropy
    }
}

__global__ void final_kernel(float* __restrict__ out, int B, int NC) {
    if (threadIdx.x == 0 && blockIdx.x == 0) {
        float invB = 1.f / (float)B;
        float ent = 0.f;
        int   np  = 0;
        for (int c = 0; c < NC; c++) {
            int g = g_counts[c];
            if (g > 0) np++;
            float b = g * invB;
            ent -= b * logf(b + 1e-5f);
        }
        out[(size_t)B * D + B]     = ent;        // cluster_size_entropy
        out[(size_t)B * D + B + 1] = (float)np;  // n_populated
    }
}

extern "C" void kernel_launch(void* const* d_in, const int* in_sizes, int n_in,
                              void* d_out, int out_size) {
    const float* enc  = (const float*)d_in[0];
    const float* cat  = (const float*)d_in[1];
    const int*   kptr = (const int*)d_in[2];
    float*       out  = (float*)d_out;

    int B  = in_sizes[0] / D;
    int NC = in_sizes[1] / B;

    // encodings passthrough
    cudaMemcpyAsync(d_out, d_in[0], (size_t)B * D * sizeof(float),
                    cudaMemcpyDeviceToDevice, 0);

    zero_kernel<<<1, MAXC>>>();
    prep_kernel<<<(B + 255) / 256, 256>>>(enc, cat, out, B, NC);
    knn_kernel<<<B / ROWS, NTHREADS>>>(enc, kptr, out, B, NC);
    final_kernel<<<1, 32>>>(out, B, NC);
}